// round 2
// baseline (speedup 1.0000x reference)
#include <cuda_runtime.h>
#include <cstdint>
#include <math.h>

// Problem constants
#define NTOK 8192   // B*S = 2*4096
#define Dh   2048   // hidden dim
#define NE   8      // experts
#define FF   8192   // ffn dim
#define TOPK 2

// ---------------- device scratch (no allocs allowed) ----------------
__device__ float g_logits[NTOK * NE];
__device__ float g_sums[NE];
__device__ int   g_sel[TOPK];
__device__ float g_rw[NTOK * TOPK];
__device__ float g_H[(size_t)NTOK * FF];   // 256 MB intermediate h (fp32)

// ---------------- helpers ----------------
__device__ __forceinline__ unsigned f2tf(float f) {
    unsigned r;
    asm("cvt.rna.tf32.f32 %0, %1;" : "=r"(r) : "f"(f));
    return r;
}

__device__ __forceinline__ float gelu_tanh(float x) {
    // jax.nn.gelu default (approximate=True)
    float x3 = x * x * x;
    float t = tanhf(0.7978845608028654f * (x + 0.044715f * x3));
    return 0.5f * x * (1.0f + t);
}

// ---------------- routing ----------------
// one block per token; warp e computes logit for expert e
__global__ void router_kernel(const float* __restrict__ x,
                              const float* __restrict__ gw) {
    int n = blockIdx.x;
    int warp = threadIdx.x >> 5, lane = threadIdx.x & 31;
    const float4* xr = (const float4*)(x + (size_t)n * Dh);
    const float4* gr = (const float4*)(gw + (size_t)warp * Dh);
    float s = 0.f;
    for (int i = lane; i < Dh / 4; i += 32) {
        float4 a = xr[i], b = gr[i];
        s += a.x * b.x + a.y * b.y + a.z * b.z + a.w * b.w;
    }
    #pragma unroll
    for (int o = 16; o; o >>= 1) s += __shfl_xor_sync(0xffffffffu, s, o);
    if (lane == 0) g_logits[n * NE + warp] = s;
}

// deterministic fixed-order column sum (no fp atomics)
__global__ void colsum_kernel() {
    int warp = threadIdx.x >> 5, lane = threadIdx.x & 31;
    if (warp >= NE) return;
    float s = 0.f;
    for (int n = lane; n < NTOK; n += 32) s += g_logits[n * NE + warp];
    #pragma unroll
    for (int o = 16; o; o >>= 1) s += __shfl_xor_sync(0xffffffffu, s, o);
    if (lane == 0) g_sums[warp] = s;
}

// serial top-2, jax.lax.top_k tie semantics (first index wins on ties)
__global__ void topk_kernel() {
    int s0 = 0; float b0 = g_sums[0];
    for (int e = 1; e < NE; e++) { float v = g_sums[e]; if (v > b0) { b0 = v; s0 = e; } }
    int s1 = -1; float b1 = -3.4e38f;
    for (int e = 0; e < NE; e++) {
        if (e == s0) continue;
        float v = g_sums[e]; if (v > b1) { b1 = v; s1 = e; }
    }
    g_sel[0] = s0; g_sel[1] = s1;
}

__global__ void weights_kernel() {
    int n = blockIdx.x * blockDim.x + threadIdx.x;
    if (n >= NTOK) return;
    float l0 = g_logits[n * NE + g_sel[0]];
    float l1 = g_logits[n * NE + g_sel[1]];
    float m = fmaxf(l0, l1);
    float e0 = expf(l0 - m), e1 = expf(l1 - m);
    float inv = 1.f / (e0 + e1);
    g_rw[n * 2 + 0] = e0 * inv;
    g_rw[n * 2 + 1] = e1 * inv;
}

// ---------------- tf32 MMA tiled GEMMs ----------------
// Block tile 128x128, K-tile 32. 8 warps in 2x4 layout, warp tile 64x32.
// mma.sync.m16n8k8 tf32, fp32 accumulate.
#define ASTR 36    // sA row stride (pad: conflict-free A-fragment LDS)
#define BSTR 136   // sB row stride (pad: conflict-free B-fragment LDS)

#define MMA_TF32(c, a, b)                                                     \
    asm volatile(                                                             \
        "mma.sync.aligned.m16n8k8.row.col.f32.tf32.tf32.f32 "                 \
        "{%0,%1,%2,%3}, {%4,%5,%6,%7}, {%8,%9}, {%0,%1,%2,%3};\n"             \
        : "+f"(c[0]), "+f"(c[1]), "+f"(c[2]), "+f"(c[3])                      \
        : "r"(a[0]), "r"(a[1]), "r"(a[2]), "r"(a[3]), "r"(b[0]), "r"(b[1]))

// GEMM1: H = gelu(X[N,D] @ W1[e][D,F] + b1[e])
__global__ __launch_bounds__(256) void gemm1_kernel(
    const float* __restrict__ X, const float* __restrict__ W1all,
    const float* __restrict__ B1all, int slot) {
    __shared__ float sA[128 * ASTR];
    __shared__ float sB[32 * BSTR];

    const int e = g_sel[slot];
    const float* __restrict__ Bg = W1all + (size_t)e * Dh * FF;
    const float* __restrict__ bias = B1all + (size_t)e * FF;

    const int tid = threadIdx.x;
    const int warp = tid >> 5, lane = tid & 31;
    const int grp = lane >> 2, tq = lane & 3;
    const int wm = warp >> 2, wn = warp & 3;
    const int m0 = blockIdx.y * 128, n0 = blockIdx.x * 128;
    const float* __restrict__ Ag = X + (size_t)m0 * Dh;

    float acc[4][4][4];
    #pragma unroll
    for (int i = 0; i < 4; i++)
        #pragma unroll
        for (int j = 0; j < 4; j++)
            #pragma unroll
            for (int r = 0; r < 4; r++) acc[i][j][r] = 0.f;

    for (int k0 = 0; k0 < Dh; k0 += 32) {
        #pragma unroll
        for (int it = 0; it < 4; it++) {            // A: 128x32
            int r = (tid >> 3) + it * 32;
            int c = (tid & 7) * 4;
            float4 v = *(const float4*)(Ag + (size_t)r * Dh + k0 + c);
            float* dst = &sA[r * ASTR + c];
            dst[0] = __uint_as_float(f2tf(v.x));
            dst[1] = __uint_as_float(f2tf(v.y));
            dst[2] = __uint_as_float(f2tf(v.z));
            dst[3] = __uint_as_float(f2tf(v.w));
        }
        #pragma unroll
        for (int it = 0; it < 4; it++) {            // B: 32x128
            int r = (tid >> 5) + it * 8;
            int c = (tid & 31) * 4;
            float4 v = *(const float4*)(Bg + (size_t)(k0 + r) * FF + n0 + c);
            float* dst = &sB[r * BSTR + c];
            dst[0] = __uint_as_float(f2tf(v.x));
            dst[1] = __uint_as_float(f2tf(v.y));
            dst[2] = __uint_as_float(f2tf(v.z));
            dst[3] = __uint_as_float(f2tf(v.w));
        }
        __syncthreads();
        #pragma unroll
        for (int ks = 0; ks < 4; ks++) {
            int kk = ks * 8;
            unsigned a[4][4];
            #pragma unroll
            for (int i = 0; i < 4; i++) {
                int rb = wm * 64 + i * 16 + grp;
                a[i][0] = __float_as_uint(sA[rb * ASTR + kk + tq]);
                a[i][1] = __float_as_uint(sA[(rb + 8) * ASTR + kk + tq]);
                a[i][2] = __float_as_uint(sA[rb * ASTR + kk + tq + 4]);
                a[i][3] = __float_as_uint(sA[(rb + 8) * ASTR + kk + tq + 4]);
            }
            unsigned b[4][2];
            #pragma unroll
            for (int j = 0; j < 4; j++) {
                int nb = wn * 32 + j * 8 + grp;
                b[j][0] = __float_as_uint(sB[(kk + tq) * BSTR + nb]);
                b[j][1] = __float_as_uint(sB[(kk + tq + 4) * BSTR + nb]);
            }
            #pragma unroll
            for (int i = 0; i < 4; i++)
                #pragma unroll
                for (int j = 0; j < 4; j++) MMA_TF32(acc[i][j], a[i], b[j]);
        }
        __syncthreads();
    }

    // epilogue: bias + gelu -> g_H
    #pragma unroll
    for (int i = 0; i < 4; i++) {
        int r0 = m0 + wm * 64 + i * 16 + grp;
        #pragma unroll
        for (int j = 0; j < 4; j++) {
            int cb = n0 + wn * 32 + j * 8 + tq * 2;
            float bi0 = bias[cb], bi1 = bias[cb + 1];
            float2 v0 = { gelu_tanh(acc[i][j][0] + bi0), gelu_tanh(acc[i][j][1] + bi1) };
            float2 v1 = { gelu_tanh(acc[i][j][2] + bi0), gelu_tanh(acc[i][j][3] + bi1) };
            *(float2*)&g_H[(size_t)r0 * FF + cb] = v0;
            *(float2*)&g_H[(size_t)(r0 + 8) * FF + cb] = v1;
        }
    }
}

// GEMM2: out (+)= rw[:,slot] * (H[N,F] @ W2[e][F,D] + b2[e])
__global__ __launch_bounds__(256) void gemm2_kernel(
    const float* __restrict__ W2all, const float* __restrict__ B2all,
    float* __restrict__ Out, int slot) {
    __shared__ float sA[128 * ASTR];
    __shared__ float sB[32 * BSTR];

    const int e = g_sel[slot];
    const float* __restrict__ Bg = W2all + (size_t)e * FF * Dh;
    const float* __restrict__ bias = B2all + (size_t)e * Dh;

    const int tid = threadIdx.x;
    const int warp = tid >> 5, lane = tid & 31;
    const int grp = lane >> 2, tq = lane & 3;
    const int wm = warp >> 2, wn = warp & 3;
    const int m0 = blockIdx.y * 128, n0 = blockIdx.x * 128;
    const float* __restrict__ Ag = g_H + (size_t)m0 * FF;

    float acc[4][4][4];
    #pragma unroll
    for (int i = 0; i < 4; i++)
        #pragma unroll
        for (int j = 0; j < 4; j++)
            #pragma unroll
            for (int r = 0; r < 4; r++) acc[i][j][r] = 0.f;

    for (int k0 = 0; k0 < FF; k0 += 32) {
        #pragma unroll
        for (int it = 0; it < 4; it++) {            // A: 128x32 from H
            int r = (tid >> 3) + it * 32;
            int c = (tid & 7) * 4;
            float4 v = *(const float4*)(Ag + (size_t)r * FF + k0 + c);
            float* dst = &sA[r * ASTR + c];
            dst[0] = __uint_as_float(f2tf(v.x));
            dst[1] = __uint_as_float(f2tf(v.y));
            dst[2] = __uint_as_float(f2tf(v.z));
            dst[3] = __uint_as_float(f2tf(v.w));
        }
        #pragma unroll
        for (int it = 0; it < 4; it++) {            // B: 32x128 from W2
            int r = (tid >> 5) + it * 8;
            int c = (tid & 31) * 4;
            float4 v = *(const float4*)(Bg + (size_t)(k0 + r) * Dh + n0 + c);
            float* dst = &sB[r * BSTR + c];
            dst[0] = __uint_as_float(f2tf(v.x));
            dst[1] = __uint_as_float(f2tf(v.y));
            dst[2] = __uint_as_float(f2tf(v.z));
            dst[3] = __uint_as_float(f2tf(v.w));
        }
        __syncthreads();
        #pragma unroll
        for (int ks = 0; ks < 4; ks++) {
            int kk = ks * 8;
            unsigned a[4][4];
            #pragma unroll
            for (int i = 0; i < 4; i++) {
                int rb = wm * 64 + i * 16 + grp;
                a[i][0] = __float_as_uint(sA[rb * ASTR + kk + tq]);
                a[i][1] = __float_as_uint(sA[(rb + 8) * ASTR + kk + tq]);
                a[i][2] = __float_as_uint(sA[rb * ASTR + kk + tq + 4]);
                a[i][3] = __float_as_uint(sA[(rb + 8) * ASTR + kk + tq + 4]);
            }
            unsigned b[4][2];
            #pragma unroll
            for (int j = 0; j < 4; j++) {
                int nb = wn * 32 + j * 8 + grp;
                b[j][0] = __float_as_uint(sB[(kk + tq) * BSTR + nb]);
                b[j][1] = __float_as_uint(sB[(kk + tq + 4) * BSTR + nb]);
            }
            #pragma unroll
            for (int i = 0; i < 4; i++)
                #pragma unroll
                for (int j = 0; j < 4; j++) MMA_TF32(acc[i][j], a[i], b[j]);
        }
        __syncthreads();
    }

    // epilogue: bias, per-token routing weight, write (slot 0) / accumulate (slot 1)
    #pragma unroll
    for (int i = 0; i < 4; i++) {
        int r0 = m0 + wm * 64 + i * 16 + grp;
        float wA = g_rw[r0 * 2 + slot];
        float wB = g_rw[(r0 + 8) * 2 + slot];
        #pragma unroll
        for (int j = 0; j < 4; j++) {
            int cb = n0 + wn * 32 + j * 8 + tq * 2;
            float bi0 = bias[cb], bi1 = bias[cb + 1];
            float o00 = wA * (acc[i][j][0] + bi0);
            float o01 = wA * (acc[i][j][1] + bi1);
            float o10 = wB * (acc[i][j][2] + bi0);
            float o11 = wB * (acc[i][j][3] + bi1);
            float2* p0 = (float2*)&Out[(size_t)r0 * Dh + cb];
            float2* p1 = (float2*)&Out[(size_t)(r0 + 8) * Dh + cb];
            if (slot == 0) {
                *p0 = make_float2(o00, o01);
                *p1 = make_float2(o10, o11);
            } else {
                float2 t0 = *p0; t0.x += o00; t0.y += o01; *p0 = t0;
                float2 t1 = *p1; t1.x += o10; t1.y += o11; *p1 = t1;
            }
        }
    }
}

// ---------------- launch ----------------
extern "C" void kernel_launch(void* const* d_in, const int* in_sizes, int n_in,
                              void* d_out, int out_size) {
    const float* x  = (const float*)d_in[0];   // [2,4096,2048]
    const float* gw = (const float*)d_in[1];   // [8,2048]
    const float* w1 = (const float*)d_in[2];   // [8,2048,8192]
    const float* b1 = (const float*)d_in[3];   // [8,8192]
    const float* w2 = (const float*)d_in[4];   // [8,8192,2048]
    const float* b2 = (const float*)d_in[5];   // [8,2048]
    float* out = (float*)d_out;                // [2,4096,2048]

    router_kernel<<<NTOK, 256>>>(x, gw);
    colsum_kernel<<<1, 256>>>();
    topk_kernel<<<1, 1>>>();
    weights_kernel<<<NTOK / 256, 256>>>();

    for (int slot = 0; slot < TOPK; ++slot) {
        gemm1_kernel<<<dim3(FF / 128, NTOK / 128), 256>>>(x, w1, b1, slot);
        gemm2_kernel<<<dim3(Dh / 128, NTOK / 128), 256>>>(w2, b2, out, slot);
    }
}

// round 7
// speedup vs baseline: 1.0672x; 1.0672x over previous
#include <cuda_runtime.h>
#include <cstdint>
#include <math.h>

// Problem constants
#define NTOK 8192   // B*S = 2*4096
#define Dh   2048   // hidden dim
#define NE   8      // experts
#define FF   8192   // ffn dim
#define TOPK 2

// ---------------- device scratch (no allocs allowed) ----------------
__device__ float g_logits[NTOK * NE];
__device__ float g_sums[NE];
__device__ int   g_sel[TOPK];
__device__ float g_rw[NTOK * TOPK];
__device__ float g_H[(size_t)NTOK * FF];   // 256 MB intermediate h (fp32)

// ---------------- helpers ----------------
__device__ __forceinline__ unsigned f2tf(float f) {
    unsigned r;
    asm("cvt.rna.tf32.f32 %0, %1;" : "=r"(r) : "f"(f));
    return r;
}

__device__ __forceinline__ float gelu_tanh(float x) {
    // jax.nn.gelu default (approximate=True)
    float x3 = x * x * x;
    float t = tanhf(0.7978845608028654f * (x + 0.044715f * x3));
    return 0.5f * x * (1.0f + t);
}

// ---------------- routing (validated round 2) ----------------
__global__ void router_kernel(const float* __restrict__ x,
                              const float* __restrict__ gw) {
    int n = blockIdx.x;
    int warp = threadIdx.x >> 5, lane = threadIdx.x & 31;
    const float4* xr = (const float4*)(x + (size_t)n * Dh);
    const float4* gr = (const float4*)(gw + (size_t)warp * Dh);
    float s = 0.f;
    for (int i = lane; i < Dh / 4; i += 32) {
        float4 a = xr[i], b = gr[i];
        s += a.x * b.x + a.y * b.y + a.z * b.z + a.w * b.w;
    }
    #pragma unroll
    for (int o = 16; o; o >>= 1) s += __shfl_xor_sync(0xffffffffu, s, o);
    if (lane == 0) g_logits[n * NE + warp] = s;
}

__global__ void colsum_kernel() {
    int warp = threadIdx.x >> 5, lane = threadIdx.x & 31;
    if (warp >= NE) return;
    float s = 0.f;
    for (int n = lane; n < NTOK; n += 32) s += g_logits[n * NE + warp];
    #pragma unroll
    for (int o = 16; o; o >>= 1) s += __shfl_xor_sync(0xffffffffu, s, o);
    if (lane == 0) g_sums[warp] = s;
}

__global__ void topk_kernel() {
    int s0 = 0; float b0 = g_sums[0];
    for (int e = 1; e < NE; e++) { float v = g_sums[e]; if (v > b0) { b0 = v; s0 = e; } }
    int s1 = -1; float b1 = -3.4e38f;
    for (int e = 0; e < NE; e++) {
        if (e == s0) continue;
        float v = g_sums[e]; if (v > b1) { b1 = v; s1 = e; }
    }
    g_sel[0] = s0; g_sel[1] = s1;
}

__global__ void weights_kernel() {
    int n = blockIdx.x * blockDim.x + threadIdx.x;
    if (n >= NTOK) return;
    float l0 = g_logits[n * NE + g_sel[0]];
    float l1 = g_logits[n * NE + g_sel[1]];
    float m = fmaxf(l0, l1);
    float e0 = expf(l0 - m), e1 = expf(l1 - m);
    float inv = 1.f / (e0 + e1);
    g_rw[n * 2 + 0] = e0 * inv;
    g_rw[n * 2 + 1] = e1 * inv;
}

// ---------------- tf32 MMA tiled GEMMs (round-2 core + reg-staged pipe) ----
// Block tile 128x128, K-tile 32. 8 warps in 2x4 layout, warp tile 64x32.
#define ASTR 36    // sA row stride (pad: conflict-free A-fragment LDS)
#define BSTR 136   // sB row stride (pad: conflict-free B-fragment LDS)

#define MMA_TF32(c, a, b)                                                     \
    asm volatile(                                                             \
        "mma.sync.aligned.m16n8k8.row.col.f32.tf32.tf32.f32 "                 \
        "{%0,%1,%2,%3}, {%4,%5,%6,%7}, {%8,%9}, {%0,%1,%2,%3};\n"             \
        : "+f"(c[0]), "+f"(c[1]), "+f"(c[2]), "+f"(c[3])                      \
        : "r"(a[0]), "r"(a[1]), "r"(a[2]), "r"(a[3]), "r"(b[0]), "r"(b[1]))

// LDG next tile into registers (addresses identical to round-2 loads)
__device__ __forceinline__ void ldg_tiles(float4 rA[4], float4 rB[4],
                                          const float* Ag, int lda,
                                          const float* Bg, int ldb, int k0) {
    int tid = threadIdx.x;
    int ra = tid >> 3, ca = (tid & 7) * 4;
    int rb = tid >> 5, cb = (tid & 31) * 4;
    #pragma unroll
    for (int it = 0; it < 4; it++)
        rA[it] = *(const float4*)(Ag + (size_t)(ra + it * 32) * lda + k0 + ca);
    #pragma unroll
    for (int it = 0; it < 4; it++)
        rB[it] = *(const float4*)(Bg + (size_t)(k0 + rb + it * 8) * ldb + cb);
}

// STS with rna->tf32 conversion (identical to round-2 store path)
__device__ __forceinline__ void sts_tiles(float* sA, float* sB,
                                          const float4 rA[4], const float4 rB[4]) {
    int tid = threadIdx.x;
    int ra = tid >> 3, ca = (tid & 7) * 4;
    int rb = tid >> 5, cb = (tid & 31) * 4;
    #pragma unroll
    for (int it = 0; it < 4; it++) {
        float* d = &sA[(ra + it * 32) * ASTR + ca];
        d[0] = __uint_as_float(f2tf(rA[it].x));
        d[1] = __uint_as_float(f2tf(rA[it].y));
        d[2] = __uint_as_float(f2tf(rA[it].z));
        d[3] = __uint_as_float(f2tf(rA[it].w));
    }
    #pragma unroll
    for (int it = 0; it < 4; it++) {
        float* d = &sB[(rb + it * 8) * BSTR + cb];
        d[0] = __uint_as_float(f2tf(rB[it].x));
        d[1] = __uint_as_float(f2tf(rB[it].y));
        d[2] = __uint_as_float(f2tf(rB[it].z));
        d[3] = __uint_as_float(f2tf(rB[it].w));
    }
}

// mainloop: acc += A[128 x K] * B[K x 128] with register-staged pipelining
__device__ __forceinline__ void mma_mainloop(float acc[4][4][4],
                                             const float* Ag, int lda,
                                             const float* Bg, int ldb,
                                             int ktiles,
                                             float* sA, float* sB) {
    const int lane = threadIdx.x & 31;
    const int warp = threadIdx.x >> 5;
    const int grp = lane >> 2, tq = lane & 3;
    const int wm = warp >> 2, wn = warp & 3;

    float4 rA[4], rB[4];
    ldg_tiles(rA, rB, Ag, lda, Bg, ldb, 0);
    sts_tiles(sA, sB, rA, rB);

    for (int kt = 0; kt < ktiles; kt++) {
        __syncthreads();                       // tile kt visible in smem
        if (kt + 1 < ktiles)                   // issue next tile's LDGs early;
            ldg_tiles(rA, rB, Ag, lda, Bg, ldb, (kt + 1) * 32);  // overlap w/ compute

        #pragma unroll
        for (int ks = 0; ks < 4; ks++) {
            int kk = ks * 8;
            unsigned a[4][4];
            #pragma unroll
            for (int i = 0; i < 4; i++) {
                int rb0 = wm * 64 + i * 16 + grp;
                a[i][0] = __float_as_uint(sA[rb0 * ASTR + kk + tq]);
                a[i][1] = __float_as_uint(sA[(rb0 + 8) * ASTR + kk + tq]);
                a[i][2] = __float_as_uint(sA[rb0 * ASTR + kk + tq + 4]);
                a[i][3] = __float_as_uint(sA[(rb0 + 8) * ASTR + kk + tq + 4]);
            }
            unsigned b[4][2];
            #pragma unroll
            for (int j = 0; j < 4; j++) {
                int nb = wn * 32 + j * 8 + grp;
                b[j][0] = __float_as_uint(sB[(kk + tq) * BSTR + nb]);
                b[j][1] = __float_as_uint(sB[(kk + tq + 4) * BSTR + nb]);
            }
            #pragma unroll
            for (int i = 0; i < 4; i++)
                #pragma unroll
                for (int j = 0; j < 4; j++) MMA_TF32(acc[i][j], a[i], b[j]);
        }

        __syncthreads();                       // all reads of tile kt done
        if (kt + 1 < ktiles)
            sts_tiles(sA, sB, rA, rB);         // overwrite with tile kt+1
    }
}

// GEMM1: H = gelu(X @ W1[e] + b1[e])   (W1 read N-major directly, as round 2)
__global__ __launch_bounds__(256, 2) void gemm1_kernel(
    const float* __restrict__ X, const float* __restrict__ W1all,
    const float* __restrict__ B1all, int slot) {
    __shared__ float sA[128 * ASTR];
    __shared__ float sB[32 * BSTR];

    const int e = g_sel[slot];
    const float* __restrict__ Bg = W1all + (size_t)e * Dh * FF + blockIdx.x * 128;
    const float* __restrict__ bias = B1all + (size_t)e * FF;
    const int m0 = blockIdx.y * 128, n0 = blockIdx.x * 128;
    const float* __restrict__ Ag = X + (size_t)m0 * Dh;

    float acc[4][4][4];
    #pragma unroll
    for (int i = 0; i < 4; i++)
        #pragma unroll
        for (int j = 0; j < 4; j++)
            #pragma unroll
            for (int r = 0; r < 4; r++) acc[i][j][r] = 0.f;

    mma_mainloop(acc, Ag, Dh, Bg, FF, Dh / 32, sA, sB);

    const int warp = threadIdx.x >> 5, lane = threadIdx.x & 31;
    const int grp = lane >> 2, tq = lane & 3;
    const int wm = warp >> 2, wn = warp & 3;
    #pragma unroll
    for (int i = 0; i < 4; i++) {
        int r0 = m0 + wm * 64 + i * 16 + grp;
        #pragma unroll
        for (int j = 0; j < 4; j++) {
            int cb = n0 + wn * 32 + j * 8 + tq * 2;
            float bi0 = bias[cb], bi1 = bias[cb + 1];
            float2 v0 = { gelu_tanh(acc[i][j][0] + bi0), gelu_tanh(acc[i][j][1] + bi1) };
            float2 v1 = { gelu_tanh(acc[i][j][2] + bi0), gelu_tanh(acc[i][j][3] + bi1) };
            *(float2*)&g_H[(size_t)r0 * FF + cb] = v0;
            *(float2*)&g_H[(size_t)(r0 + 8) * FF + cb] = v1;
        }
    }
}

// GEMM2: out (+)= rw[:,slot] * (H @ W2[e] + b2[e])
__global__ __launch_bounds__(256, 2) void gemm2_kernel(
    const float* __restrict__ W2all, const float* __restrict__ B2all,
    float* __restrict__ Out, int slot) {
    __shared__ float sA[128 * ASTR];
    __shared__ float sB[32 * BSTR];

    const int e = g_sel[slot];
    const float* __restrict__ Bg = W2all + (size_t)e * FF * Dh + blockIdx.x * 128;
    const float* __restrict__ bias = B2all + (size_t)e * Dh;
    const int m0 = blockIdx.y * 128, n0 = blockIdx.x * 128;
    const float* __restrict__ Ag = g_H + (size_t)m0 * FF;

    float acc[4][4][4];
    #pragma unroll
    for (int i = 0; i < 4; i++)
        #pragma unroll
        for (int j = 0; j < 4; j++)
            #pragma unroll
            for (int r = 0; r < 4; r++) acc[i][j][r] = 0.f;

    mma_mainloop(acc, Ag, FF, Bg, Dh, FF / 32, sA, sB);

    const int warp = threadIdx.x >> 5, lane = threadIdx.x & 31;
    const int grp = lane >> 2, tq = lane & 3;
    const int wm = warp >> 2, wn = warp & 3;
    #pragma unroll
    for (int i = 0; i < 4; i++) {
        int r0 = m0 + wm * 64 + i * 16 + grp;
        float wA = g_rw[r0 * 2 + slot];
        float wB = g_rw[(r0 + 8) * 2 + slot];
        #pragma unroll
        for (int j = 0; j < 4; j++) {
            int cb = n0 + wn * 32 + j * 8 + tq * 2;
            float bi0 = bias[cb], bi1 = bias[cb + 1];
            float o00 = wA * (acc[i][j][0] + bi0);
            float o01 = wA * (acc[i][j][1] + bi1);
            float o10 = wB * (acc[i][j][2] + bi0);
            float o11 = wB * (acc[i][j][3] + bi1);
            float2* p0 = (float2*)&Out[(size_t)r0 * Dh + cb];
            float2* p1 = (float2*)&Out[(size_t)(r0 + 8) * Dh + cb];
            if (slot == 0) {
                *p0 = make_float2(o00, o01);
                *p1 = make_float2(o10, o11);
            } else {
                float2 t0 = *p0; t0.x += o00; t0.y += o01; *p0 = t0;
                float2 t1 = *p1; t1.x += o10; t1.y += o11; *p1 = t1;
            }
        }
    }
}

// ---------------- launch ----------------
extern "C" void kernel_launch(void* const* d_in, const int* in_sizes, int n_in,
                              void* d_out, int out_size) {
    const float* x  = (const float*)d_in[0];   // [2,4096,2048]
    const float* gw = (const float*)d_in[1];   // [8,2048]
    const float* w1 = (const float*)d_in[2];   // [8,2048,8192]
    const float* b1 = (const float*)d_in[3];   // [8,8192]
    const float* w2 = (const float*)d_in[4];   // [8,8192,2048]
    const float* b2 = (const float*)d_in[5];   // [8,2048]
    float* out = (float*)d_out;                // [2,4096,2048]

    router_kernel<<<NTOK, 256>>>(x, gw);
    colsum_kernel<<<1, 256>>>();
    topk_kernel<<<1, 1>>>();
    weights_kernel<<<NTOK / 256, 256>>>();

    for (int slot = 0; slot < TOPK; ++slot) {
        gemm1_kernel<<<dim3(FF / 128, NTOK / 128), 256>>>(x, w1, b1, slot);
        gemm2_kernel<<<dim3(Dh / 128, NTOK / 128), 256>>>(w2, b2, out, slot);
    }
}